// round 3
// baseline (speedup 1.0000x reference)
#include <cuda_runtime.h>

#define NB 64
#define NEe 8978
#define NE2e 4489
#define NN1 (NB*NEe)
#define NN2 (NB*NE2e)
#define SLOPEc 0.33f
#define GSB 1184

__device__ float g_s1[NN1], g_s2[NN1], g_s3[NN1];
__device__ float g_Y0[NN2*32], g_Y1[NN2*32], g_Y2[NN2*32], g_Y3[NN2*32];
__device__ float g_R1[NN2*32], g_R2[NN2*32], g_O1[NN2*32];
__device__ float g_w0[NN2], g_w1[NN2], g_w2[NN2], g_w3[NN2];
__device__ float g_r1[NN2], g_r2[NN2], g_raw2[NN2];
__device__ float g_A[4096], g_a0[128], g_aV[128];
__device__ double g_st0[14*16], g_sum1[32*16], g_sq1[32*16], g_st2[2*16];
__device__ float g_scale0[32], g_shift0[32], g_scale1[32], g_shift1[32], g_bn2s[2];
__device__ float g_h1raw[64*256], g_h1[64*256], g_h2raw[64*128];

__constant__ float c_C[16] = {1.f,0.f,0.f,0.f,
                              1.f,-1.f,0.f,0.f,
                              1.f,-2.f,0.5f,0.f,
                              1.f,-3.f,1.5f,-0.16666666666666666f};

__device__ __forceinline__ float leaky(float v){ return v>0.f? v : SLOPEc*v; }

// ---- prep: combined weights + zero stat accumulators ----
__global__ void k_prep(const float* __restrict__ W0, const float* __restrict__ W1,
                       const float* __restrict__ W2){
    int t = blockIdx.x*blockDim.x + threadIdx.x;
    int stride = gridDim.x*blockDim.x;
    for (int idx=t; idx<4096; idx+=stride){
        int m = idx>>10, ic = idx&1023;
        float s=0.f;
        #pragma unroll
        for (int k=0;k<4;k++) s = fmaf(c_C[k*4+m], W1[k*1024+ic], s);
        g_A[idx]=s;
    }
    for (int idx=t; idx<128; idx+=stride){
        int m = idx>>5, c = idx&31;
        float s0=0.f, sv=0.f;
        #pragma unroll
        for (int k=0;k<4;k++){
            float cc = c_C[k*4+m];
            s0 = fmaf(cc, W0[k*32+c], s0);
            sv = fmaf(cc, W2[k*32+c], sv);   // W2 shape (4,32,1)
        }
        g_a0[idx]=s0; g_aV[idx]=sv;
    }
    for (int idx=t; idx<14*16; idx+=stride) g_st0[idx]=0.0;
    for (int idx=t; idx<32*16; idx+=stride){ g_sum1[idx]=0.0; g_sq1[idx]=0.0; }
    for (int idx=t; idx<2*16;  idx+=stride) g_st2[idx]=0.0;
}

// ---- scalar matvec body: acc += sum_{q<16} ew[16i+q]*v[src[16i+q]] ----
__device__ __forceinline__ void smv_body(int i, const float* __restrict__ v,
                                         const int* __restrict__ src,
                                         const float* __restrict__ ew, float& acc){
    const int4*   sp = reinterpret_cast<const int4*>(src) + i*4;
    const float4* wp = reinterpret_cast<const float4*>(ew) + i*4;
    #pragma unroll
    for (int q=0;q<4;q++){
        int4 s = __ldg(sp+q); float4 w = __ldg(wp+q);
        acc = fmaf(w.x, __ldg(v+s.x), acc);
        acc = fmaf(w.y, __ldg(v+s.y), acc);
        acc = fmaf(w.z, __ldg(v+s.z), acc);
        acc = fmaf(w.w, __ldg(v+s.w), acc);
    }
}

__global__ void k_s1(const int* __restrict__ src, const float* __restrict__ ew,
                     const float* __restrict__ x){
    int i = blockIdx.x*blockDim.x+threadIdx.x; if (i>=NN1) return;
    float a=0.f; smv_body(i, x, src, ew, a); g_s1[i]=a;
}
__global__ void k_s2(const int* __restrict__ src, const float* __restrict__ ew){
    int i = blockIdx.x*blockDim.x+threadIdx.x; if (i>=NN1) return;
    float a=0.f; smv_body(i, g_s1, src, ew, a); g_s2[i]=a;
}
__global__ void k_s3stats(const int* __restrict__ src, const float* __restrict__ ew,
                          const float* __restrict__ x){
    int stride = gridDim.x*blockDim.x;
    float ls[14];
    #pragma unroll
    for (int j=0;j<14;j++) ls[j]=0.f;
    for (int i = blockIdx.x*blockDim.x+threadIdx.x; i<NN1; i+=stride){
        float a=0.f; smv_body(i, g_s2, src, ew, a);
        g_s3[i]=a;
        float v0=__ldg(x+i), v1=g_s1[i], v2=g_s2[i], v3=a;
        ls[0]+=v0; ls[1]+=v1; ls[2]+=v2; ls[3]+=v3;
        ls[4]+=v0*v0; ls[5]+=v0*v1; ls[6]+=v0*v2; ls[7]+=v0*v3;
        ls[8]+=v1*v1; ls[9]+=v1*v2; ls[10]+=v1*v3;
        ls[11]+=v2*v2; ls[12]+=v2*v3; ls[13]+=v3*v3;
    }
    __shared__ float sh[14];
    if (threadIdx.x<14) sh[threadIdx.x]=0.f;
    __syncthreads();
    #pragma unroll
    for (int j=0;j<14;j++){
        #pragma unroll
        for (int r=16;r;r>>=1) ls[j] += __shfl_xor_sync(0xffffffffu, ls[j], r);
    }
    if ((threadIdx.x&31)==0){
        #pragma unroll
        for (int j=0;j<14;j++) atomicAdd(&sh[j], ls[j]);
    }
    __syncthreads();
    if (threadIdx.x<14)
        atomicAdd(&g_st0[threadIdx.x*16 + (blockIdx.x&15)], (double)sh[threadIdx.x]);
}

__global__ void k_fin0(const float* __restrict__ b0, const float* __restrict__ g0,
                       const float* __restrict__ be0){
    int c = threadIdx.x; if (c>=32) return;
    double st[14];
    for (int j=0;j<14;j++){ double s=0; for (int q=0;q<16;q++) s+=g_st0[j*16+q]; st[j]=s; }
    double invN = 1.0/(double)NN1;
    double mu[4];
    for (int m=0;m<4;m++) mu[m]=st[m]*invN;
    double cov[4][4]; int idx=4;
    for (int m=0;m<4;m++) for (int mm=m;mm<4;mm++){
        double cc = st[idx]*invN - mu[m]*mu[mm];
        cov[m][mm]=cc; cov[mm][m]=cc; idx++;
    }
    double a[4];
    for (int m=0;m<4;m++) a[m]=(double)g_a0[m*32+c];
    double proj = 0.0;
    for (int m=0;m<4;m++) proj += mu[m]*a[m];
    double var=0;
    for (int m=0;m<4;m++) for (int mm=0;mm<4;mm++) var += a[m]*a[mm]*cov[m][mm];
    double sc = (double)g0[c]/sqrt(var+1e-5);
    g_scale0[c]=(float)sc;
    g_shift0[c]=(float)((double)be0[c] - proj*sc);
}

// ---- fused pool + channel-mix GEMM (Y_m = X1 @ A_m) ----
__global__ void __launch_bounds__(128) k_poolmix(const float* __restrict__ x){
    int lane = threadIdx.x&31;
    float A0[32],A1r[32],A2r[32],A3r[32];
    #pragma unroll
    for (int i=0;i<32;i++){
        A0[i]=g_A[i*32+lane];        A1r[i]=g_A[1024+i*32+lane];
        A2r[i]=g_A[2048+i*32+lane];  A3r[i]=g_A[3072+i*32+lane];
    }
    float a0=g_a0[lane], a1=g_a0[32+lane], a2=g_a0[64+lane], a3=g_a0[96+lane];
    float sc=g_scale0[lane], sf=g_shift0[lane];
    int w  = (blockIdx.x*blockDim.x+threadIdx.x)>>5;
    int nw = (gridDim.x*blockDim.x)>>5;
    for (int n=w; n<NN2; n+=nw){
        int b = n / NE2e; int e2 = n - b*NE2e; int m0 = b*NEe + 2*e2;
        float s0a=__ldg(x+m0),   s1a=g_s1[m0],   s2a=g_s2[m0],   s3a=g_s3[m0];
        float s0b=__ldg(x+m0+1), s1b=g_s1[m0+1], s2b=g_s2[m0+1], s3b=g_s3[m0+1];
        float ra = fmaf(s0a,a0, fmaf(s1a,a1, fmaf(s2a,a2, s3a*a3)));
        float rb = fmaf(s0b,a0, fmaf(s1b,a1, fmaf(s2b,a2, s3b*a3)));
        float xv = fmaxf(leaky(fmaf(ra,sc,sf)), leaky(fmaf(rb,sc,sf)));
        float y0=0.f,y1=0.f,y2=0.f,y3=0.f;
        #pragma unroll
        for (int i=0;i<32;i++){
            float v = __shfl_sync(0xffffffffu, xv, i);
            y0=fmaf(v,A0[i],y0); y1=fmaf(v,A1r[i],y1);
            y2=fmaf(v,A2r[i],y2); y3=fmaf(v,A3r[i],y3);
        }
        g_Y0[n*32+lane]=y0; g_Y1[n*32+lane]=y1;
        g_Y2[n*32+lane]=y2; g_Y3[n*32+lane]=y3;
    }
}

// ---- 32-channel matvec body ----
__device__ __forceinline__ float mv32_body(int n, int lane, const float* __restrict__ v,
                                           const int* __restrict__ src,
                                           const float* __restrict__ ew, float acc){
    int q = n*16 + (lane&15);
    int   s_r = __ldg(src+q);
    float w_r = __ldg(ew+q);
    #pragma unroll
    for (int j=0;j<16;j++){
        int   s = __shfl_sync(0xffffffffu, s_r, j);
        float w = __shfl_sync(0xffffffffu, w_r, j);
        acc = fmaf(w, __ldg(v + s*32 + lane), acc);
    }
    return acc;
}

__global__ void k_mvA(const int* __restrict__ src, const float* __restrict__ ew){
    int w=(blockIdx.x*blockDim.x+threadIdx.x)>>5; if (w>=NN2) return;
    int lane=threadIdx.x&31;
    g_R1[w*32+lane] = mv32_body(w, lane, g_Y3, src, ew, g_Y2[w*32+lane]);
}
__global__ void k_mvB(const int* __restrict__ src, const float* __restrict__ ew){
    int w=(blockIdx.x*blockDim.x+threadIdx.x)>>5; if (w>=NN2) return;
    int lane=threadIdx.x&31;
    g_R2[w*32+lane] = mv32_body(w, lane, g_R1, src, ew, g_Y1[w*32+lane]);
}
__global__ void k_mvC(const int* __restrict__ src, const float* __restrict__ ew,
                      const float* __restrict__ b1){
    int lane=threadIdx.x&31;
    int w =(blockIdx.x*blockDim.x+threadIdx.x)>>5;
    int nw=(gridDim.x*blockDim.x)>>5;
    float bias=__ldg(b1+lane);
    float ps=0.f,pq=0.f;
    for (int n=w;n<NN2;n+=nw){
        float acc = mv32_body(n,lane,g_R2,src,ew, g_Y0[n*32+lane]+bias);
        g_O1[n*32+lane]=acc;
        ps+=acc; pq+=acc*acc;
    }
    __shared__ float ss[32], sq2[32];
    if (threadIdx.x<32){ ss[threadIdx.x]=0.f; sq2[threadIdx.x]=0.f; }
    __syncthreads();
    atomicAdd(&ss[lane], ps); atomicAdd(&sq2[lane], pq);
    __syncthreads();
    if (threadIdx.x<32){
        int slot=blockIdx.x&15;
        atomicAdd(&g_sum1[threadIdx.x*16+slot], (double)ss[threadIdx.x]);
        atomicAdd(&g_sq1[threadIdx.x*16+slot],  (double)sq2[threadIdx.x]);
    }
}

__global__ void k_fin1(const float* __restrict__ g1, const float* __restrict__ be1){
    int c=threadIdx.x; if (c>=32) return;
    double s=0,q=0;
    for (int slot=0;slot<16;slot++){ s+=g_sum1[c*16+slot]; q+=g_sq1[c*16+slot]; }
    double invN = 1.0/(double)NN2;
    double mean=s*invN, var=q*invN-mean*mean;
    double sc=(double)g1[c]/sqrt(var+1e-5);
    g_scale1[c]=(float)sc; g_shift1[c]=(float)((double)be1[c]-mean*sc);
}

// ---- layer2: per-node 32->scalar projections w_m = act(bn(O1)) . aV_m ----
__global__ void k_mix2(){
    int w=(blockIdx.x*blockDim.x+threadIdx.x)>>5; if (w>=NN2) return;
    int lane=threadIdx.x&31;
    float o=g_O1[w*32+lane];
    float x2=leaky(fmaf(g_scale1[lane], o, g_shift1[lane]));
    float p0=x2*g_aV[lane],     p1=x2*g_aV[32+lane];
    float p2=x2*g_aV[64+lane],  p3=x2*g_aV[96+lane];
    #pragma unroll
    for (int r=16;r;r>>=1){
        p0+=__shfl_xor_sync(0xffffffffu,p0,r); p1+=__shfl_xor_sync(0xffffffffu,p1,r);
        p2+=__shfl_xor_sync(0xffffffffu,p2,r); p3+=__shfl_xor_sync(0xffffffffu,p3,r);
    }
    if (lane==0){ g_w0[w]=p0; g_w1[w]=p1; g_w2[w]=p2; g_w3[w]=p3; }
}

__global__ void k_sc1(const int* __restrict__ src, const float* __restrict__ ew){
    int i = blockIdx.x*blockDim.x+threadIdx.x; if (i>=NN2) return;
    float a=g_w2[i]; smv_body(i, g_w3, src, ew, a); g_r1[i]=a;
}
__global__ void k_sc2(const int* __restrict__ src, const float* __restrict__ ew){
    int i = blockIdx.x*blockDim.x+threadIdx.x; if (i>=NN2) return;
    float a=g_w1[i]; smv_body(i, g_r1, src, ew, a); g_r2[i]=a;
}
__global__ void k_sc3(const int* __restrict__ src, const float* __restrict__ ew,
                      const float* __restrict__ b2){
    int stride = gridDim.x*blockDim.x;
    float bias=__ldg(b2);
    float ps=0.f,pq=0.f;
    for (int i = blockIdx.x*blockDim.x+threadIdx.x; i<NN2; i+=stride){
        float a=g_w0[i]+bias; smv_body(i, g_r2, src, ew, a);
        g_raw2[i]=a; ps+=a; pq+=a*a;
    }
    __shared__ float sh[2];
    if (threadIdx.x<2) sh[threadIdx.x]=0.f;
    __syncthreads();
    #pragma unroll
    for (int r=16;r;r>>=1){ ps+=__shfl_xor_sync(0xffffffffu,ps,r); pq+=__shfl_xor_sync(0xffffffffu,pq,r); }
    if ((threadIdx.x&31)==0){ atomicAdd(&sh[0],ps); atomicAdd(&sh[1],pq); }
    __syncthreads();
    if (threadIdx.x<2)
        atomicAdd(&g_st2[threadIdx.x*16 + (blockIdx.x&15)], (double)sh[threadIdx.x]);
}

__global__ void k_finS(const float* __restrict__ g2, const float* __restrict__ be2){
    if (threadIdx.x!=0) return;
    double s=0,q=0;
    for (int slot=0;slot<16;slot++){ s+=g_st2[slot]; q+=g_st2[16+slot]; }
    double invN=1.0/(double)NN2;
    double mean=s*invN, var=q*invN-mean*mean;
    double sc=(double)g2[0]/sqrt(var+1e-5);
    g_bn2s[0]=(float)sc; g_bn2s[1]=(float)((double)be2[0]-mean*sc);
}

// ---- MLP ----
__global__ void k_mlp1(const float* __restrict__ W, const float* __restrict__ bb){
    __shared__ float shx[NE2e];
    int b = blockIdx.x, t = threadIdx.x;
    float sc=g_bn2s[0], sf=g_bn2s[1];
    for (int i=t;i<NE2e;i+=256){
        float v = fmaf(g_raw2[b*NE2e+i], sc, sf);
        shx[i] = leaky(v);
    }
    __syncthreads();
    float acc = __ldg(bb+t);
    int i=0;
    for (; i+4<=NE2e; i+=4){
        acc = fmaf(shx[i],   __ldg(W+(i  )*256+t), acc);
        acc = fmaf(shx[i+1], __ldg(W+(i+1)*256+t), acc);
        acc = fmaf(shx[i+2], __ldg(W+(i+2)*256+t), acc);
        acc = fmaf(shx[i+3], __ldg(W+(i+3)*256+t), acc);
    }
    for (; i<NE2e; i++) acc = fmaf(shx[i], __ldg(W+i*256+t), acc);
    g_h1raw[b*256+t]=acc;
}

__global__ void k_bn1(const float* __restrict__ g, const float* __restrict__ be){
    int c=threadIdx.x;
    float s=0.f,q=0.f;
    #pragma unroll 8
    for (int b=0;b<64;b++){ float v=g_h1raw[b*256+c]; s+=v; q+=v*v; }
    float mean=s*(1.f/64.f), var=q*(1.f/64.f)-mean*mean;
    float sc=__ldg(g+c)*rsqrtf(var+1e-5f), sf=__ldg(be+c)-mean*sc;
    for (int b=0;b<64;b++){
        float v=fmaf(g_h1raw[b*256+c],sc,sf);
        g_h1[b*256+c]= v>0.f? v:0.f;
    }
}

__global__ void k_mlp2(const float* __restrict__ W, const float* __restrict__ bb){
    __shared__ float shx[256];
    int b = blockIdx.x, t = threadIdx.x;
    for (int i=t;i<256;i+=128) shx[i]=g_h1[b*256+i];
    __syncthreads();
    float acc=__ldg(bb+t);
    #pragma unroll 8
    for (int i=0;i<256;i++) acc = fmaf(shx[i], __ldg(W+i*128+t), acc);
    g_h2raw[b*128+t]=acc;
}

__global__ void k_bn2out(const float* __restrict__ g, const float* __restrict__ be,
                         const float* __restrict__ W3, const float* __restrict__ b3,
                         float* __restrict__ out){
    __shared__ float sh2[64*128];
    int c=threadIdx.x;
    float s=0.f,q=0.f;
    #pragma unroll 8
    for (int b=0;b<64;b++){ float v=g_h2raw[b*128+c]; s+=v; q+=v*v; }
    float mean=s*(1.f/64.f), var=q*(1.f/64.f)-mean*mean;
    float sc=__ldg(g+c)*rsqrtf(var+1e-5f), sf=__ldg(be+c)-mean*sc;
    for (int b=0;b<64;b++){
        float v=fmaf(g_h2raw[b*128+c],sc,sf);
        sh2[b*128+c]= v>0.f? v:0.f;
    }
    __syncthreads();
    if (c<64){
        float acc=__ldg(b3);
        #pragma unroll 8
        for (int j=0;j<128;j++) acc=fmaf(sh2[c*128+j], __ldg(W3+j), acc);
        out[c]=acc;
    }
}

extern "C" void kernel_launch(void* const* d_in, const int* in_sizes, int n_in,
                              void* d_out, int out_size){
    const float* x_s  = (const float*)d_in[0];
    const int*   ei1  = (const int*)d_in[1];
    const float* ew1  = (const float*)d_in[2];
    const int*   ei2  = (const int*)d_in[3];
    const float* ew2  = (const float*)d_in[4];
    const float* W0   = (const float*)d_in[5];
    const float* b0   = (const float*)d_in[6];
    const float* g0   = (const float*)d_in[7];
    const float* be0  = (const float*)d_in[8];
    const float* W1   = (const float*)d_in[9];
    const float* b1   = (const float*)d_in[10];
    const float* g1   = (const float*)d_in[11];
    const float* be1  = (const float*)d_in[12];
    const float* W2   = (const float*)d_in[13];
    const float* b2   = (const float*)d_in[14];
    const float* g2   = (const float*)d_in[15];
    const float* be2  = (const float*)d_in[16];
    const float* l1W  = (const float*)d_in[17];
    const float* l1b  = (const float*)d_in[18];
    const float* bn1g = (const float*)d_in[19];
    const float* bn1b = (const float*)d_in[20];
    const float* l2W  = (const float*)d_in[21];
    const float* l2b  = (const float*)d_in[22];
    const float* bn2g = (const float*)d_in[23];
    const float* bn2b = (const float*)d_in[24];
    const float* l3W  = (const float*)d_in[25];
    const float* l3b  = (const float*)d_in[26];
    float* out = (float*)d_out;

    const int* src1 = ei1;                 // edge_index_s[0]
    const int* src2 = ei2;                 // edge_index_s1[0]

    k_prep<<<32,256>>>(W0, W1, W2);

    int nb1 = (NN1+255)/256;
    k_s1<<<nb1,256>>>(src1, ew1, x_s);
    k_s2<<<nb1,256>>>(src1, ew1);
    k_s3stats<<<GSB,256>>>(src1, ew1, x_s);
    k_fin0<<<1,32>>>(b0, g0, be0);

    k_poolmix<<<GSB,128>>>(x_s);

    int nbw = (NN2*32+255)/256;            // warp-per-node kernels
    k_mvA<<<nbw,256>>>(src2, ew2);
    k_mvB<<<nbw,256>>>(src2, ew2);
    k_mvC<<<GSB,256>>>(src2, ew2, b1);
    k_fin1<<<1,32>>>(g1, be1);

    k_mix2<<<nbw,256>>>();
    int nb2 = (NN2+255)/256;
    k_sc1<<<nb2,256>>>(src2, ew2);
    k_sc2<<<nb2,256>>>(src2, ew2);
    k_sc3<<<GSB,256>>>(src2, ew2, b2);
    k_finS<<<1,32>>>(g2, be2);

    k_mlp1<<<64,256>>>(l1W, l1b);
    k_bn1<<<1,256>>>(bn1g, bn1b);
    k_mlp2<<<64,128>>>(l2W, l2b);
    k_bn2out<<<1,128>>>(bn2g, bn2b, l3W, l3b, out);
}

// round 4
// speedup vs baseline: 1.0008x; 1.0008x over previous
#include <cuda_runtime.h>

#define NB 64
#define NEe 8978
#define NE2e 4489
#define NN1 (NB*NEe)
#define NN2 (NB*NE2e)
#define SLOPEc 0.33f
#define GSB 1184

__device__ float g_s1[NN1], g_s2[NN1], g_s3[NN1];
__device__ float g_Y0[NN2*32], g_Y1[NN2*32], g_Y2[NN2*32], g_Y3[NN2*32];
__device__ float g_R1[NN2*32], g_R2[NN2*32], g_O1[NN2*32];
__device__ float g_w0[NN2], g_w1[NN2], g_w2[NN2], g_w3[NN2];
__device__ float g_r1[NN2], g_r2[NN2], g_raw2[NN2];
__device__ float g_A[4096], g_a0[128], g_aV[128];
__device__ double g_st0[14*16], g_sum1[32*16], g_sq1[32*16], g_st2[2*16];
__device__ float g_scale0[32], g_shift0[32], g_scale1[32], g_shift1[32], g_bn2s[2];
__device__ float g_h1raw[64*256], g_h1[64*256], g_h2raw[64*128];

__constant__ float c_C[16] = {1.f,0.f,0.f,0.f,
                              1.f,-1.f,0.f,0.f,
                              1.f,-2.f,0.5f,0.f,
                              1.f,-3.f,1.5f,-0.16666666666666666f};

__device__ __forceinline__ float leaky(float v){ return v>0.f? v : SLOPEc*v; }

// ---- prep: combined weights + zero stat accumulators ----
__global__ void k_prep(const float* __restrict__ W0, const float* __restrict__ W1,
                       const float* __restrict__ W2){
    int t = blockIdx.x*blockDim.x + threadIdx.x;
    int stride = gridDim.x*blockDim.x;
    for (int idx=t; idx<4096; idx+=stride){
        int m = idx>>10, ic = idx&1023;
        float s=0.f;
        #pragma unroll
        for (int k=0;k<4;k++) s = fmaf(c_C[k*4+m], W1[k*1024+ic], s);
        g_A[idx]=s;
    }
    for (int idx=t; idx<128; idx+=stride){
        int m = idx>>5, c = idx&31;
        float s0=0.f, sv=0.f;
        #pragma unroll
        for (int k=0;k<4;k++){
            float cc = c_C[k*4+m];
            s0 = fmaf(cc, W0[k*32+c], s0);
            sv = fmaf(cc, W2[k*32+c], sv);   // W2 shape (4,32,1)
        }
        g_a0[idx]=s0; g_aV[idx]=sv;
    }
    for (int idx=t; idx<14*16; idx+=stride) g_st0[idx]=0.0;
    for (int idx=t; idx<32*16; idx+=stride){ g_sum1[idx]=0.0; g_sq1[idx]=0.0; }
    for (int idx=t; idx<2*16;  idx+=stride) g_st2[idx]=0.0;
}

// ---- scalar matvec body: acc += sum_{q<16} ew[16i+q]*v[src[16i+q]] ----
__device__ __forceinline__ void smv_body(int i, const float* __restrict__ v,
                                         const int* __restrict__ src,
                                         const float* __restrict__ ew, float& acc){
    const int4*   sp = reinterpret_cast<const int4*>(src) + i*4;
    const float4* wp = reinterpret_cast<const float4*>(ew) + i*4;
    #pragma unroll
    for (int q=0;q<4;q++){
        int4 s = __ldg(sp+q); float4 w = __ldg(wp+q);
        acc = fmaf(w.x, __ldg(v+s.x), acc);
        acc = fmaf(w.y, __ldg(v+s.y), acc);
        acc = fmaf(w.z, __ldg(v+s.z), acc);
        acc = fmaf(w.w, __ldg(v+s.w), acc);
    }
}

__global__ void k_s1(const int* __restrict__ src, const float* __restrict__ ew,
                     const float* __restrict__ x){
    int i = blockIdx.x*blockDim.x+threadIdx.x; if (i>=NN1) return;
    float a=0.f; smv_body(i, x, src, ew, a); g_s1[i]=a;
}
__global__ void k_s2(const int* __restrict__ src, const float* __restrict__ ew){
    int i = blockIdx.x*blockDim.x+threadIdx.x; if (i>=NN1) return;
    float a=0.f; smv_body(i, g_s1, src, ew, a); g_s2[i]=a;
}
__global__ void k_s3stats(const int* __restrict__ src, const float* __restrict__ ew,
                          const float* __restrict__ x){
    int stride = gridDim.x*blockDim.x;
    float ls[14];
    #pragma unroll
    for (int j=0;j<14;j++) ls[j]=0.f;
    for (int i = blockIdx.x*blockDim.x+threadIdx.x; i<NN1; i+=stride){
        float a=0.f; smv_body(i, g_s2, src, ew, a);
        g_s3[i]=a;
        float v0=__ldg(x+i), v1=g_s1[i], v2=g_s2[i], v3=a;
        ls[0]+=v0; ls[1]+=v1; ls[2]+=v2; ls[3]+=v3;
        ls[4]+=v0*v0; ls[5]+=v0*v1; ls[6]+=v0*v2; ls[7]+=v0*v3;
        ls[8]+=v1*v1; ls[9]+=v1*v2; ls[10]+=v1*v3;
        ls[11]+=v2*v2; ls[12]+=v2*v3; ls[13]+=v3*v3;
    }
    __shared__ float sh[14];
    if (threadIdx.x<14) sh[threadIdx.x]=0.f;
    __syncthreads();
    #pragma unroll
    for (int j=0;j<14;j++){
        #pragma unroll
        for (int r=16;r;r>>=1) ls[j] += __shfl_xor_sync(0xffffffffu, ls[j], r);
    }
    if ((threadIdx.x&31)==0){
        #pragma unroll
        for (int j=0;j<14;j++) atomicAdd(&sh[j], ls[j]);
    }
    __syncthreads();
    if (threadIdx.x<14)
        atomicAdd(&g_st0[threadIdx.x*16 + (blockIdx.x&15)], (double)sh[threadIdx.x]);
}

__global__ void k_fin0(const float* __restrict__ b0, const float* __restrict__ g0,
                       const float* __restrict__ be0){
    int c = threadIdx.x; if (c>=32) return;
    double st[14];
    for (int j=0;j<14;j++){ double s=0; for (int q=0;q<16;q++) s+=g_st0[j*16+q]; st[j]=s; }
    double invN = 1.0/(double)NN1;
    double mu[4];
    for (int m=0;m<4;m++) mu[m]=st[m]*invN;
    double cov[4][4]; int idx=4;
    for (int m=0;m<4;m++) for (int mm=m;mm<4;mm++){
        double cc = st[idx]*invN - mu[m]*mu[mm];
        cov[m][mm]=cc; cov[mm][m]=cc; idx++;
    }
    double a[4];
    for (int m=0;m<4;m++) a[m]=(double)g_a0[m*32+c];
    double proj = 0.0;
    for (int m=0;m<4;m++) proj += mu[m]*a[m];
    double var=0;
    for (int m=0;m<4;m++) for (int mm=0;mm<4;mm++) var += a[m]*a[mm]*cov[m][mm];
    double sc = (double)g0[c]/sqrt(var+1e-5);
    g_scale0[c]=(float)sc;
    g_shift0[c]=(float)((double)be0[c] - proj*sc);
}

// ---- fused pool + channel-mix GEMM (Y_m = X1 @ A_m) ----
__global__ void __launch_bounds__(128) k_poolmix(const float* __restrict__ x){
    int lane = threadIdx.x&31;
    float A0[32],A1r[32],A2r[32],A3r[32];
    #pragma unroll
    for (int i=0;i<32;i++){
        A0[i]=g_A[i*32+lane];        A1r[i]=g_A[1024+i*32+lane];
        A2r[i]=g_A[2048+i*32+lane];  A3r[i]=g_A[3072+i*32+lane];
    }
    float a0=g_a0[lane], a1=g_a0[32+lane], a2=g_a0[64+lane], a3=g_a0[96+lane];
    float sc=g_scale0[lane], sf=g_shift0[lane];
    int w  = (blockIdx.x*blockDim.x+threadIdx.x)>>5;
    int nw = (gridDim.x*blockDim.x)>>5;
    for (int n=w; n<NN2; n+=nw){
        int b = n / NE2e; int e2 = n - b*NE2e; int m0 = b*NEe + 2*e2;
        float s0a=__ldg(x+m0),   s1a=g_s1[m0],   s2a=g_s2[m0],   s3a=g_s3[m0];
        float s0b=__ldg(x+m0+1), s1b=g_s1[m0+1], s2b=g_s2[m0+1], s3b=g_s3[m0+1];
        float ra = fmaf(s0a,a0, fmaf(s1a,a1, fmaf(s2a,a2, s3a*a3)));
        float rb = fmaf(s0b,a0, fmaf(s1b,a1, fmaf(s2b,a2, s3b*a3)));
        float xv = fmaxf(leaky(fmaf(ra,sc,sf)), leaky(fmaf(rb,sc,sf)));
        float y0=0.f,y1=0.f,y2=0.f,y3=0.f;
        #pragma unroll
        for (int i=0;i<32;i++){
            float v = __shfl_sync(0xffffffffu, xv, i);
            y0=fmaf(v,A0[i],y0); y1=fmaf(v,A1r[i],y1);
            y2=fmaf(v,A2r[i],y2); y3=fmaf(v,A3r[i],y3);
        }
        g_Y0[n*32+lane]=y0; g_Y1[n*32+lane]=y1;
        g_Y2[n*32+lane]=y2; g_Y3[n*32+lane]=y3;
    }
}

// ---- 32-channel matvec body ----
__device__ __forceinline__ float mv32_body(int n, int lane, const float* __restrict__ v,
                                           const int* __restrict__ src,
                                           const float* __restrict__ ew, float acc){
    int q = n*16 + (lane&15);
    int   s_r = __ldg(src+q);
    float w_r = __ldg(ew+q);
    #pragma unroll
    for (int j=0;j<16;j++){
        int   s = __shfl_sync(0xffffffffu, s_r, j);
        float w = __shfl_sync(0xffffffffu, w_r, j);
        acc = fmaf(w, __ldg(v + s*32 + lane), acc);
    }
    return acc;
}

__global__ void k_mvA(const int* __restrict__ src, const float* __restrict__ ew){
    int w=(blockIdx.x*blockDim.x+threadIdx.x)>>5; if (w>=NN2) return;
    int lane=threadIdx.x&31;
    g_R1[w*32+lane] = mv32_body(w, lane, g_Y3, src, ew, g_Y2[w*32+lane]);
}
__global__ void k_mvB(const int* __restrict__ src, const float* __restrict__ ew){
    int w=(blockIdx.x*blockDim.x+threadIdx.x)>>5; if (w>=NN2) return;
    int lane=threadIdx.x&31;
    g_R2[w*32+lane] = mv32_body(w, lane, g_R1, src, ew, g_Y1[w*32+lane]);
}
__global__ void k_mvC(const int* __restrict__ src, const float* __restrict__ ew,
                      const float* __restrict__ b1){
    int lane=threadIdx.x&31;
    int w =(blockIdx.x*blockDim.x+threadIdx.x)>>5;
    int nw=(gridDim.x*blockDim.x)>>5;
    float bias=__ldg(b1+lane);
    float ps=0.f,pq=0.f;
    for (int n=w;n<NN2;n+=nw){
        float acc = mv32_body(n,lane,g_R2,src,ew, g_Y0[n*32+lane]+bias);
        g_O1[n*32+lane]=acc;
        ps+=acc; pq+=acc*acc;
    }
    __shared__ float ss[32], sq2[32];
    if (threadIdx.x<32){ ss[threadIdx.x]=0.f; sq2[threadIdx.x]=0.f; }
    __syncthreads();
    atomicAdd(&ss[lane], ps); atomicAdd(&sq2[lane], pq);
    __syncthreads();
    if (threadIdx.x<32){
        int slot=blockIdx.x&15;
        atomicAdd(&g_sum1[threadIdx.x*16+slot], (double)ss[threadIdx.x]);
        atomicAdd(&g_sq1[threadIdx.x*16+slot],  (double)sq2[threadIdx.x]);
    }
}

__global__ void k_fin1(const float* __restrict__ g1, const float* __restrict__ be1){
    int c=threadIdx.x; if (c>=32) return;
    double s=0,q=0;
    for (int slot=0;slot<16;slot++){ s+=g_sum1[c*16+slot]; q+=g_sq1[c*16+slot]; }
    double invN = 1.0/(double)NN2;
    double mean=s*invN, var=q*invN-mean*mean;
    double sc=(double)g1[c]/sqrt(var+1e-5);
    g_scale1[c]=(float)sc; g_shift1[c]=(float)((double)be1[c]-mean*sc);
}

// ---- layer2: per-node 32->scalar projections w_m = act(bn(O1)) . aV_m ----
__global__ void k_mix2(){
    int w=(blockIdx.x*blockDim.x+threadIdx.x)>>5; if (w>=NN2) return;
    int lane=threadIdx.x&31;
    float o=g_O1[w*32+lane];
    float x2=leaky(fmaf(g_scale1[lane], o, g_shift1[lane]));
    float p0=x2*g_aV[lane],     p1=x2*g_aV[32+lane];
    float p2=x2*g_aV[64+lane],  p3=x2*g_aV[96+lane];
    #pragma unroll
    for (int r=16;r;r>>=1){
        p0+=__shfl_xor_sync(0xffffffffu,p0,r); p1+=__shfl_xor_sync(0xffffffffu,p1,r);
        p2+=__shfl_xor_sync(0xffffffffu,p2,r); p3+=__shfl_xor_sync(0xffffffffu,p3,r);
    }
    if (lane==0){ g_w0[w]=p0; g_w1[w]=p1; g_w2[w]=p2; g_w3[w]=p3; }
}

__global__ void k_sc1(const int* __restrict__ src, const float* __restrict__ ew){
    int i = blockIdx.x*blockDim.x+threadIdx.x; if (i>=NN2) return;
    float a=g_w2[i]; smv_body(i, g_w3, src, ew, a); g_r1[i]=a;
}
__global__ void k_sc2(const int* __restrict__ src, const float* __restrict__ ew){
    int i = blockIdx.x*blockDim.x+threadIdx.x; if (i>=NN2) return;
    float a=g_w1[i]; smv_body(i, g_r1, src, ew, a); g_r2[i]=a;
}
__global__ void k_sc3(const int* __restrict__ src, const float* __restrict__ ew,
                      const float* __restrict__ b2){
    int stride = gridDim.x*blockDim.x;
    float bias=__ldg(b2);
    float ps=0.f,pq=0.f;
    for (int i = blockIdx.x*blockDim.x+threadIdx.x; i<NN2; i+=stride){
        float a=g_w0[i]+bias; smv_body(i, g_r2, src, ew, a);
        g_raw2[i]=a; ps+=a; pq+=a*a;
    }
    __shared__ float sh[2];
    if (threadIdx.x<2) sh[threadIdx.x]=0.f;
    __syncthreads();
    #pragma unroll
    for (int r=16;r;r>>=1){ ps+=__shfl_xor_sync(0xffffffffu,ps,r); pq+=__shfl_xor_sync(0xffffffffu,pq,r); }
    if ((threadIdx.x&31)==0){ atomicAdd(&sh[0],ps); atomicAdd(&sh[1],pq); }
    __syncthreads();
    if (threadIdx.x<2)
        atomicAdd(&g_st2[threadIdx.x*16 + (blockIdx.x&15)], (double)sh[threadIdx.x]);
}

__global__ void k_finS(const float* __restrict__ g2, const float* __restrict__ be2){
    if (threadIdx.x!=0) return;
    double s=0,q=0;
    for (int slot=0;slot<16;slot++){ s+=g_st2[slot]; q+=g_st2[16+slot]; }
    double invN=1.0/(double)NN2;
    double mean=s*invN, var=q*invN-mean*mean;
    double sc=(double)g2[0]/sqrt(var+1e-5);
    g_bn2s[0]=(float)sc; g_bn2s[1]=(float)((double)be2[0]-mean*sc);
}

// ---- MLP ----
__global__ void k_mlp1(const float* __restrict__ W, const float* __restrict__ bb){
    __shared__ float shx[NE2e];
    int b = blockIdx.x, t = threadIdx.x;
    float sc=g_bn2s[0], sf=g_bn2s[1];
    for (int i=t;i<NE2e;i+=256){
        float v = fmaf(g_raw2[b*NE2e+i], sc, sf);
        shx[i] = leaky(v);
    }
    __syncthreads();
    float acc = __ldg(bb+t);
    int i=0;
    for (; i+4<=NE2e; i+=4){
        acc = fmaf(shx[i],   __ldg(W+(i  )*256+t), acc);
        acc = fmaf(shx[i+1], __ldg(W+(i+1)*256+t), acc);
        acc = fmaf(shx[i+2], __ldg(W+(i+2)*256+t), acc);
        acc = fmaf(shx[i+3], __ldg(W+(i+3)*256+t), acc);
    }
    for (; i<NE2e; i++) acc = fmaf(shx[i], __ldg(W+i*256+t), acc);
    g_h1raw[b*256+t]=acc;
}

__global__ void k_bn1(const float* __restrict__ g, const float* __restrict__ be){
    int c=threadIdx.x;
    float s=0.f,q=0.f;
    #pragma unroll 8
    for (int b=0;b<64;b++){ float v=g_h1raw[b*256+c]; s+=v; q+=v*v; }
    float mean=s*(1.f/64.f), var=q*(1.f/64.f)-mean*mean;
    float sc=__ldg(g+c)*rsqrtf(var+1e-5f), sf=__ldg(be+c)-mean*sc;
    for (int b=0;b<64;b++){
        float v=fmaf(g_h1raw[b*256+c],sc,sf);
        g_h1[b*256+c]= v>0.f? v:0.f;
    }
}

__global__ void k_mlp2(const float* __restrict__ W, const float* __restrict__ bb){
    __shared__ float shx[256];
    int b = blockIdx.x, t = threadIdx.x;
    for (int i=t;i<256;i+=128) shx[i]=g_h1[b*256+i];
    __syncthreads();
    float acc=__ldg(bb+t);
    #pragma unroll 8
    for (int i=0;i<256;i++) acc = fmaf(shx[i], __ldg(W+i*128+t), acc);
    g_h2raw[b*128+t]=acc;
}

__global__ void k_bn2out(const float* __restrict__ g, const float* __restrict__ be,
                         const float* __restrict__ W3, const float* __restrict__ b3,
                         float* __restrict__ out){
    __shared__ float sh2[64*128];
    int c=threadIdx.x;
    float s=0.f,q=0.f;
    #pragma unroll 8
    for (int b=0;b<64;b++){ float v=g_h2raw[b*128+c]; s+=v; q+=v*v; }
    float mean=s*(1.f/64.f), var=q*(1.f/64.f)-mean*mean;
    float sc=__ldg(g+c)*rsqrtf(var+1e-5f), sf=__ldg(be+c)-mean*sc;
    for (int b=0;b<64;b++){
        float v=fmaf(g_h2raw[b*128+c],sc,sf);
        sh2[b*128+c]= v>0.f? v:0.f;
    }
    __syncthreads();
    if (c<64){
        float acc=__ldg(b3);
        #pragma unroll 8
        for (int j=0;j<128;j++) acc=fmaf(sh2[c*128+j], __ldg(W3+j), acc);
        out[c]=acc;
    }
}

extern "C" void kernel_launch(void* const* d_in, const int* in_sizes, int n_in,
                              void* d_out, int out_size){
    const float* x_s  = (const float*)d_in[0];
    const int*   ei1  = (const int*)d_in[1];
    const float* ew1  = (const float*)d_in[2];
    const int*   ei2  = (const int*)d_in[3];
    const float* ew2  = (const float*)d_in[4];
    const float* W0   = (const float*)d_in[5];
    const float* b0   = (const float*)d_in[6];
    const float* g0   = (const float*)d_in[7];
    const float* be0  = (const float*)d_in[8];
    const float* W1   = (const float*)d_in[9];
    const float* b1   = (const float*)d_in[10];
    const float* g1   = (const float*)d_in[11];
    const float* be1  = (const float*)d_in[12];
    const float* W2   = (const float*)d_in[13];
    const float* b2   = (const float*)d_in[14];
    const float* g2   = (const float*)d_in[15];
    const float* be2  = (const float*)d_in[16];
    const float* l1W  = (const float*)d_in[17];
    const float* l1b  = (const float*)d_in[18];
    const float* bn1g = (const float*)d_in[19];
    const float* bn1b = (const float*)d_in[20];
    const float* l2W  = (const float*)d_in[21];
    const float* l2b  = (const float*)d_in[22];
    const float* bn2g = (const float*)d_in[23];
    const float* bn2b = (const float*)d_in[24];
    const float* l3W  = (const float*)d_in[25];
    const float* l3b  = (const float*)d_in[26];
    float* out = (float*)d_out;

    const int* src1 = ei1;                 // edge_index_s[0]
    const int* src2 = ei2;                 // edge_index_s1[0]

    k_prep<<<32,256>>>(W0, W1, W2);

    int nb1 = (NN1+255)/256;
    k_s1<<<nb1,256>>>(src1, ew1, x_s);
    k_s2<<<nb1,256>>>(src1, ew1);
    k_s3stats<<<GSB,256>>>(src1, ew1, x_s);
    k_fin0<<<1,32>>>(b0, g0, be0);

    k_poolmix<<<GSB,128>>>(x_s);

    int nbw = (NN2*32+255)/256;            // warp-per-node kernels
    k_mvA<<<nbw,256>>>(src2, ew2);
    k_mvB<<<nbw,256>>>(src2, ew2);
    k_mvC<<<GSB,256>>>(src2, ew2, b1);
    k_fin1<<<1,32>>>(g1, be1);

    k_mix2<<<nbw,256>>>();
    int nb2 = (NN2+255)/256;
    k_sc1<<<nb2,256>>>(src2, ew2);
    k_sc2<<<nb2,256>>>(src2, ew2);
    k_sc3<<<GSB,256>>>(src2, ew2, b2);
    k_finS<<<1,32>>>(g2, be2);

    k_mlp1<<<64,256>>>(l1W, l1b);
    k_bn1<<<1,256>>>(bn1g, bn1b);
    k_mlp2<<<64,128>>>(l2W, l2b);
    k_bn2out<<<1,128>>>(bn2g, bn2b, l3W, l3b, out);
}